// round 5
// baseline (speedup 1.0000x reference)
#include <cuda_runtime.h>
#include <cuda_bf16.h>
#include <math.h>
#include <stdint.h>

#define NF    20000
#define NMB   5000
#define EFFN  100000
#define EMFN  80000
#define DIMV  64
#define KWN   512
#define SLAB  500
#define NSLAB 40

// ---------------- device scratch (__device__ globals; no allocations) ----------------
__device__ float    g_h0[(size_t)EFFN * KWN];     // 204.8 MB
__device__ float    g_h [(size_t)EFFN * KWN];     // 204.8 MB
__device__ float    g_M [(size_t)SLAB * KWN * DIMV]; // 65.5 MB
__device__ float    g_W2T[(size_t)DIMV * KWN * DIMV]; // 8 MB  W2T[d][k*64+f] = Wk2[k][d*64+f]
__device__ float    g_q [NF * DIMV];
__device__ float    g_kk[NMB * DIMV];
__device__ float    g_v [NMB * DIMV];
__device__ float    g_c [NF * DIMV];              // x_flow @ reshape(bk2,64,64)
__device__ float    g_score[EMFN];
__device__ float    g_av[EMFN];
__device__ unsigned g_mkey[NF];
__device__ float    g_z[NF];
__device__ float    g_xc[NF * DIMV];
__device__ float    g_base[NF * DIMV];
__device__ float    g_aggr[NF * DIMV];
__device__ int      g_cnt[NF];
__device__ int      g_off[NF + 1];
__device__ int      g_pos[NF];
__device__ int      g_perm[EFFN];
__device__ float    g_ss[2 * DIMV];

// ---------------- helpers ----------------
__device__ __forceinline__ unsigned kenc(float f) {
    unsigned b = __float_as_uint(f);
    return (b & 0x80000000u) ? ~b : (b | 0x80000000u);
}
__device__ __forceinline__ float kdec(unsigned u) {
    return (u & 0x80000000u) ? __uint_as_float(u ^ 0x80000000u) : __uint_as_float(~u);
}
__device__ __forceinline__ float silu(float y) { return y / (1.f + expf(-y)); }

// ---------------- tiny utility kernels ----------------
__global__ void zero_u32(unsigned* p, int n) {
    for (int i = blockIdx.x * blockDim.x + threadIdx.x; i < n; i += gridDim.x * blockDim.x)
        p[i] = 0u;
}

// W2T[d*32768 + k*64 + f] = Wk2[k*4096 + d*64 + f]
__global__ void permute_wk2(const float* __restrict__ Wk2) {
    int idx = blockIdx.x * blockDim.x + threadIdx.x;
    if (idx >= KWN * DIMV * DIMV) return;
    int k = idx >> 12;          // /4096
    int r = idx & 4095;
    int d = r >> 6;
    int f = r & 63;
    g_W2T[(size_t)d * (KWN * DIMV) + k * DIMV + f] = Wk2[idx];
}

// ---------------- generic tiled SGEMM: C = act(A[M,K] @ B[K,N] + bias) ----------------
// float4 fast path only when K % 4 == 0 (row starts 16B-aligned); scalar otherwise.
template <bool RELU>
__global__ void __launch_bounds__(256, 2)
sgemm(const float* __restrict__ A, const float* __restrict__ B,
      const float* __restrict__ bias, float* __restrict__ C,
      int M, int N, int K) {
    __shared__ float As[16][132];   // transposed [k][m], padded
    __shared__ float Bs[16][128];
    int bm = blockIdx.y * 128, bn = blockIdx.x * 128;
    int tid = threadIdx.x;
    int tr = tid >> 4, tc = tid & 15;
    bool k4 = ((K & 3) == 0);

    float acc[8][8];
#pragma unroll
    for (int i = 0; i < 8; i++)
#pragma unroll
        for (int j = 0; j < 8; j++) acc[i][j] = 0.f;

    for (int kt = 0; kt < K; kt += 16) {
        // A tile 128x16 -> As[k][m]
#pragma unroll
        for (int l = 0; l < 2; l++) {
            int lin = tid + l * 256;
            int row = lin >> 2;
            int kq  = (lin & 3) * 4;
            float4 v = make_float4(0.f, 0.f, 0.f, 0.f);
            int gr = bm + row;
            if (gr < M) {
                int k0 = kt + kq;
                if (k4 && k0 + 3 < K) {
                    v = *(const float4*)&A[(size_t)gr * K + k0];
                } else {
                    float t0[4] = {0.f, 0.f, 0.f, 0.f};
#pragma unroll
                    for (int i = 0; i < 4; i++)
                        if (k0 + i < K) t0[i] = A[(size_t)gr * K + k0 + i];
                    v = make_float4(t0[0], t0[1], t0[2], t0[3]);
                }
            }
            As[kq + 0][row] = v.x; As[kq + 1][row] = v.y;
            As[kq + 2][row] = v.z; As[kq + 3][row] = v.w;
        }
        // B tile 16x128 (all B matrices have N % 4 == 0 -> rows 16B-aligned)
#pragma unroll
        for (int l = 0; l < 2; l++) {
            int lin = tid + l * 256;
            int kr = lin >> 5;
            int nq = (lin & 31) * 4;
            float4 v = make_float4(0.f, 0.f, 0.f, 0.f);
            int gk = kt + kr, gn = bn + nq;
            if (gk < K && gn + 3 < N)
                v = *(const float4*)&B[(size_t)gk * N + gn];
            *(float4*)&Bs[kr][nq] = v;
        }
        __syncthreads();
#pragma unroll
        for (int k = 0; k < 16; k++) {
            float a[8], b[8];
            *(float4*)&a[0] = *(const float4*)&As[k][tr * 8];
            *(float4*)&a[4] = *(const float4*)&As[k][tr * 8 + 4];
            *(float4*)&b[0] = *(const float4*)&Bs[k][tc * 8];
            *(float4*)&b[4] = *(const float4*)&Bs[k][tc * 8 + 4];
#pragma unroll
            for (int i = 0; i < 8; i++)
#pragma unroll
                for (int j = 0; j < 8; j++) acc[i][j] = fmaf(a[i], b[j], acc[i][j]);
        }
        __syncthreads();
    }
#pragma unroll
    for (int i = 0; i < 8; i++) {
        int gr = bm + tr * 8 + i;
        if (gr >= M) continue;
#pragma unroll
        for (int j = 0; j < 8; j++) {
            int gn = bn + tc * 8 + j;
            if (gn >= N) continue;
            float v = acc[i][j];
            if (bias) v += bias[gn];
            if (RELU) v = fmaxf(v, 0.f);
            C[(size_t)gr * N + gn] = v;
        }
    }
}

// ---------------- attention path ----------------
__global__ void score_kernel(const int* __restrict__ ei_mf, const float* __restrict__ ea_mf,
                             const float* __restrict__ We) {
    __shared__ float sWe[6 * 64];
    int tid = threadIdx.x;
    for (int i = tid; i < 6 * 64; i += blockDim.x) sWe[i] = We[i];
    __syncthreads();
    int e = blockIdx.x * 8 + (tid >> 5);
    if (e >= EMFN) return;
    int l = tid & 31;
    int src = ei_mf[e];
    int dst = ei_mf[EMFN + e];
    float ke0 = g_kk[src * 64 + l];
    float ke1 = g_kk[src * 64 + 32 + l];
#pragma unroll
    for (int j = 0; j < 6; j++) {
        float ea = ea_mf[e * 6 + j];
        ke0 = fmaf(ea, sWe[j * 64 + l], ke0);
        ke1 = fmaf(ea, sWe[j * 64 + 32 + l], ke1);
    }
    float s = g_q[dst * 64 + l] * ke0 + g_q[dst * 64 + 32 + l] * ke1;
#pragma unroll
    for (int off = 16; off; off >>= 1) s += __shfl_down_sync(0xffffffffu, s, off);
    if (l == 0) {
        s *= 0.125f;   // 1/sqrt(64)
        g_score[e] = s;
        atomicMax(&g_mkey[dst], kenc(s));
    }
}

__global__ void exp_kernel(const int* __restrict__ ei_mf) {
    int e = blockIdx.x * blockDim.x + threadIdx.x;
    if (e >= EMFN) return;
    int dst = ei_mf[EMFN + e];
    float a = expf(g_score[e] - kdec(g_mkey[dst]));
    g_av[e] = a;
    atomicAdd(&g_z[dst], a);
}

__global__ void xcacc_kernel(const int* __restrict__ ei_mf) {
    int e = blockIdx.x * 8 + (threadIdx.x >> 5);
    if (e >= EMFN) return;
    int l = threadIdx.x & 31;
    int src = ei_mf[e];
    int dst = ei_mf[EMFN + e];
    float alpha = g_av[e] / (g_z[dst] + 1e-9f);
    atomicAdd(&g_xc[dst * 64 + l],      alpha * g_v[src * 64 + l]);
    atomicAdd(&g_xc[dst * 64 + 32 + l], alpha * g_v[src * 64 + 32 + l]);
}

// base = x_flow@Wroot + broot + x_cross@Wo + bo
__global__ void dual64_kernel(const float* __restrict__ x, const float* __restrict__ Wroot,
                              const float* __restrict__ broot, const float* __restrict__ Wo,
                              const float* __restrict__ bo) {
    __shared__ float sWr[64 * 64], sWo[64 * 64], sx[4][64], sxc[4][64];
    int tid = threadIdx.x;
    for (int i = tid; i < 4096; i += 256) { sWr[i] = Wroot[i]; sWo[i] = Wo[i]; }
    int r0 = blockIdx.x * 4;
    {
        int rr = tid >> 6, cc = tid & 63;
        int gr = r0 + rr;
        sx[rr][cc]  = (gr < NF) ? x[gr * 64 + cc]    : 0.f;
        sxc[rr][cc] = (gr < NF) ? g_xc[gr * 64 + cc] : 0.f;
    }
    __syncthreads();
    int rr = tid >> 6, cc = tid & 63;
    int gr = r0 + rr;
    if (gr < NF) {
        float s = broot[cc] + bo[cc];
#pragma unroll 8
        for (int d = 0; d < 64; d++)
            s += sx[rr][d] * sWr[d * 64 + cc] + sxc[rr][d] * sWo[d * 64 + cc];
        g_base[gr * 64 + cc] = s;
    }
}

// ---------------- CSR by src over ff-edges ----------------
__global__ void cnt_kernel(const int* __restrict__ ei_ff) {
    int e = blockIdx.x * blockDim.x + threadIdx.x;
    if (e < EFFN) atomicAdd(&g_cnt[ei_ff[e]], 1);
}

__global__ void scan_kernel() {
    __shared__ int s[1024];
    __shared__ int carry;
    int tid = threadIdx.x;
    if (tid == 0) carry = 0;
    __syncthreads();
    for (int base = 0; base < NF; base += 1024) {
        int i = base + tid;
        int v = (i < NF) ? g_cnt[i] : 0;
        s[tid] = v;
        __syncthreads();
        for (int off = 1; off < 1024; off <<= 1) {
            int t = (tid >= off) ? s[tid - off] : 0;
            __syncthreads();
            s[tid] += t;
            __syncthreads();
        }
        if (i < NF) { int ex = carry + s[tid] - v; g_off[i] = ex; g_pos[i] = ex; }
        __syncthreads();
        if (tid == 0) carry += s[1023];
        __syncthreads();
    }
    if (tid == 0) g_off[NF] = carry;
}

__global__ void fill_kernel(const int* __restrict__ ei_ff) {
    int e = blockIdx.x * blockDim.x + threadIdx.x;
    if (e < EFFN) {
        int p = atomicAdd(&g_pos[ei_ff[e]], 1);
        g_perm[p] = e;
    }
}

// ---------------- phase B: per-node msg = h[e] @ M[node] -> atomic aggr[dst] ----------------
__global__ void __launch_bounds__(256)
msg_kernel(const int* __restrict__ ei_ff, int slab) {
    __shared__ float Ms[128][64];
    __shared__ float hs[8][128];
    __shared__ float red[8][4][64];
    int tid = threadIdx.x;
    int nl = blockIdx.x;                // node within slab
    int n  = slab * SLAB + nl;
    int begin = g_off[n], end = g_off[n + 1];
    if (begin == end) return;
    int f = tid & 63, slice = tid >> 6;
    const float* Mrow = g_M + (size_t)nl * (KWN * DIMV);
    float cbias = g_c[n * 64 + f];

    for (int e0 = begin; e0 < end; e0 += 8) {
        int ec = min(8, end - e0);
        float acc[8];
#pragma unroll
        for (int j = 0; j < 8; j++) acc[j] = 0.f;

        for (int kt = 0; kt < 4; kt++) {
#pragma unroll
            for (int l = 0; l < 8; l++) {
                int lin = tid + l * 256;
                int k = lin >> 4;
                int fq = (lin & 15) * 4;
                *(float4*)&Ms[k][fq] = *(const float4*)&Mrow[(kt * 128 + k) * 64 + fq];
            }
            {
                int j  = tid >> 5;
                int kq = (tid & 31) * 4;
                float4 v = make_float4(0.f, 0.f, 0.f, 0.f);
                if (j < ec) {
                    int e = g_perm[e0 + j];
                    v = *(const float4*)&g_h[(size_t)e * KWN + kt * 128 + kq];
                }
                *(float4*)&hs[j][kq] = v;
            }
            __syncthreads();
#pragma unroll
            for (int kk2 = 0; kk2 < 32; kk2++) {
                int k = slice * 32 + kk2;
                float m = Ms[k][f];
                for (int j = 0; j < 8; j++)
                    if (j < ec) acc[j] = fmaf(hs[j][k], m, acc[j]);
            }
            __syncthreads();
        }
        for (int j = 0; j < ec; j++) red[j][slice][f] = acc[j];
        __syncthreads();
        for (int jb = 0; jb < ec; jb += 4) {
            int j = jb + (tid >> 6);
            if (j < ec) {
                float s = red[j][0][f] + red[j][1][f] + red[j][2][f] + red[j][3][f] + cbias;
                int e = g_perm[e0 + j];
                int dst = ei_ff[EFFN + e];
                atomicAdd(&g_aggr[dst * 64 + f], s);
            }
        }
        __syncthreads();
    }
}

// ---------------- FiLM epilogue ----------------
__global__ void ss_kernel(const float* __restrict__ tau, const float* __restrict__ Wt1,
                          const float* __restrict__ bt1, const float* __restrict__ Wt2,
                          const float* __restrict__ bt2) {
    __shared__ float temb[64];
    int tid = threadIdx.x;
    if (tid < 64) temb[tid] = silu(tau[0] * Wt1[tid] + bt1[tid]);
    __syncthreads();
    if (tid < 128) {
        float s = bt2[tid];
        for (int d = 0; d < 64; d++) s += temb[d] * Wt2[d * 128 + tid];
        g_ss[tid] = s;
    }
}

__global__ void final_kernel(float* __restrict__ out) {
    int idx = blockIdx.x * blockDim.x + threadIdx.x;
    if (idx >= NF * 64) return;
    int fcol = idx & 63;
    float g = g_base[idx] + g_aggr[idx];
    g = fmaxf(g, 0.f);
    float y = g * (1.f + g_ss[fcol]) + g_ss[64 + fcol];
    out[idx] = silu(y);
}

// ---------------- host ----------------
extern "C" void kernel_launch(void* const* d_in, const int* in_sizes, int n_in,
                              void* d_out, int out_size) {
    const float* x_flow = (const float*)d_in[0];
    const float* x_memb = (const float*)d_in[1];
    const int *ei_ff, *ei_mf;
    const float *ea_ff, *ea_mf, *tau;
    if (in_sizes[2] == 2 * EFFN) {         // reference-signature order
        ei_ff = (const int*)d_in[2];  ea_ff = (const float*)d_in[3];
        ei_mf = (const int*)d_in[4];  ea_mf = (const float*)d_in[5];
        tau   = (const float*)d_in[6];
    } else {                               // setup_inputs dict order
        ea_ff = (const float*)d_in[2]; ea_mf = (const float*)d_in[3];
        tau   = (const float*)d_in[4];
        ei_ff = (const int*)d_in[5];   ei_mf = (const int*)d_in[6];
    }
    const float* Wk0   = (const float*)d_in[7];
    const float* bk0   = (const float*)d_in[8];
    const float* Wk1   = (const float*)d_in[9];
    const float* bk1   = (const float*)d_in[10];
    const float* Wk2   = (const float*)d_in[11];
    const float* bk2   = (const float*)d_in[12];
    const float* Wroot = (const float*)d_in[13];
    const float* broot = (const float*)d_in[14];
    const float* Wq    = (const float*)d_in[15];
    const float* Wkk   = (const float*)d_in[16];
    const float* Wv    = (const float*)d_in[17];
    const float* We    = (const float*)d_in[18];
    const float* Wo    = (const float*)d_in[19];
    const float* bo    = (const float*)d_in[20];
    const float* Wt1   = (const float*)d_in[21];
    const float* bt1   = (const float*)d_in[22];
    const float* Wt2   = (const float*)d_in[23];
    const float* bt2   = (const float*)d_in[24];
    float* out = (float*)d_out;

    unsigned *p_mkey; float *p_z, *p_xc, *p_aggr; int* p_cnt;
    cudaGetSymbolAddress((void**)&p_mkey, g_mkey);
    cudaGetSymbolAddress((void**)&p_z,    g_z);
    cudaGetSymbolAddress((void**)&p_xc,   g_xc);
    cudaGetSymbolAddress((void**)&p_aggr, g_aggr);
    cudaGetSymbolAddress((void**)&p_cnt,  g_cnt);
    float *p_q, *p_kk, *p_v, *p_c, *p_h0, *p_h, *p_M, *p_W2T;
    cudaGetSymbolAddress((void**)&p_q,   g_q);
    cudaGetSymbolAddress((void**)&p_kk,  g_kk);
    cudaGetSymbolAddress((void**)&p_v,   g_v);
    cudaGetSymbolAddress((void**)&p_c,   g_c);
    cudaGetSymbolAddress((void**)&p_h0,  g_h0);
    cudaGetSymbolAddress((void**)&p_h,   g_h);
    cudaGetSymbolAddress((void**)&p_M,   g_M);
    cudaGetSymbolAddress((void**)&p_W2T, g_W2T);

    // init
    zero_u32<<<160, 256>>>(p_mkey, NF);
    zero_u32<<<160, 256>>>((unsigned*)p_z, NF);
    zero_u32<<<640, 256>>>((unsigned*)p_xc, NF * 64);
    zero_u32<<<640, 256>>>((unsigned*)p_aggr, NF * 64);
    zero_u32<<<160, 256>>>((unsigned*)p_cnt, NF);
    permute_wk2<<<(KWN * DIMV * DIMV + 255) / 256, 256>>>(Wk2);

    // small GEMMs: q, k, v, c
    {
        dim3 g1(1, (NF + 127) / 128);
        sgemm<false><<<g1, 256>>>(x_flow, Wq, nullptr, p_q, NF, 64, 64);
        dim3 g2(1, (NMB + 127) / 128);
        sgemm<false><<<g2, 256>>>(x_memb, Wkk, nullptr, p_kk, NMB, 64, 64);
        sgemm<false><<<g2, 256>>>(x_memb, Wv, nullptr, p_v, NMB, 64, 64);
        sgemm<false><<<g1, 256>>>(x_flow, bk2, nullptr, p_c, NF, 64, 64);
    }

    // attention path
    score_kernel<<<(EMFN + 7) / 8, 256>>>(ei_mf, ea_mf, We);
    exp_kernel<<<(EMFN + 255) / 256, 256>>>(ei_mf);
    xcacc_kernel<<<(EMFN + 7) / 8, 256>>>(ei_mf);
    dual64_kernel<<<(NF + 3) / 4, 256>>>(x_flow, Wroot, broot, Wo, bo);

    // edge MLP
    sgemm<true><<<dim3(4, (EFFN + 127) / 128), 256>>>(ea_ff, Wk0, bk0, p_h0, EFFN, KWN, 6);
    sgemm<true><<<dim3(4, (EFFN + 127) / 128), 256>>>(p_h0, Wk1, bk1, p_h, EFFN, KWN, KWN);

    // CSR by src
    cnt_kernel<<<(EFFN + 255) / 256, 256>>>(ei_ff);
    scan_kernel<<<1, 1024>>>();
    fill_kernel<<<(EFFN + 255) / 256, 256>>>(ei_ff);

    // slabbed phase A (M = x_slab @ W2T) + phase B (msg/aggr)
    for (int s = 0; s < NSLAB; s++) {
        sgemm<false><<<dim3(KWN * DIMV / 128, (SLAB + 127) / 128), 256>>>(
            x_flow + (size_t)s * SLAB * DIMV, p_W2T, nullptr, p_M,
            SLAB, KWN * DIMV, DIMV);
        msg_kernel<<<SLAB, 256>>>(ei_ff, s);
    }

    // FiLM epilogue
    ss_kernel<<<1, 128>>>(tau, Wt1, bt1, Wt2, bt2);
    final_kernel<<<(NF * 64 + 255) / 256, 256>>>(out);
}

// round 6
// speedup vs baseline: 1.2067x; 1.2067x over previous
#include <cuda_runtime.h>
#include <cuda_bf16.h>
#include <math.h>
#include <stdint.h>

#define NF    20000
#define NMB   5000
#define EFFN  100000
#define EMFN  80000
#define DIMV  64
#define KWN   512
#define SLAB  500
#define NSLAB 40

typedef unsigned long long u64t;

// ---------------- device scratch (__device__ globals; no allocations) ----------------
__device__ float    g_h0[(size_t)EFFN * KWN];     // 204.8 MB
__device__ float    g_h [(size_t)EFFN * KWN];     // 204.8 MB
__device__ float    g_M [(size_t)SLAB * KWN * DIMV]; // 65.5 MB
__device__ float    g_W2T[(size_t)DIMV * KWN * DIMV]; // 8 MB  W2T[d][k*64+f] = Wk2[k][d*64+f]
__device__ float    g_q [NF * DIMV];
__device__ float    g_kk[NMB * DIMV];
__device__ float    g_v [NMB * DIMV];
__device__ float    g_c [NF * DIMV];              // x_flow @ reshape(bk2,64,64)
__device__ float    g_score[EMFN];
__device__ float    g_av[EMFN];
__device__ unsigned g_mkey[NF];
__device__ float    g_z[NF];
__device__ float    g_xc[NF * DIMV];
__device__ float    g_base[NF * DIMV];
__device__ float    g_aggr[NF * DIMV];
__device__ int      g_cnt[NF];
__device__ int      g_off[NF + 1];
__device__ int      g_pos[NF];
__device__ int      g_perm[EFFN];
__device__ float    g_ss[2 * DIMV];

// ---------------- helpers ----------------
__device__ __forceinline__ unsigned kenc(float f) {
    unsigned b = __float_as_uint(f);
    return (b & 0x80000000u) ? ~b : (b | 0x80000000u);
}
__device__ __forceinline__ float kdec(unsigned u) {
    return (u & 0x80000000u) ? __uint_as_float(u ^ 0x80000000u) : __uint_as_float(~u);
}
__device__ __forceinline__ float silu(float y) { return y / (1.f + expf(-y)); }

// packed fp32x2 (Blackwell FFMA2 — only reachable via PTX)
__device__ __forceinline__ u64t pack_dup(float x) {
    u64t r;
    asm("mov.b64 %0, {%1, %1};" : "=l"(r) : "r"(__float_as_uint(x)));
    return r;
}
__device__ __forceinline__ u64t pack2(float lo, float hi) {
    u64t r;
    asm("mov.b64 %0, {%1, %2};" : "=l"(r) : "r"(__float_as_uint(lo)), "r"(__float_as_uint(hi)));
    return r;
}
__device__ __forceinline__ void fma2(u64t& d, u64t a, u64t b) {
    asm("fma.rn.f32x2 %0, %1, %2, %0;" : "+l"(d) : "l"(a), "l"(b));
}

// ---------------- tiny utility kernels ----------------
__global__ void zero_u32(unsigned* p, int n) {
    for (int i = blockIdx.x * blockDim.x + threadIdx.x; i < n; i += gridDim.x * blockDim.x)
        p[i] = 0u;
}

// W2T[d*32768 + k*64 + f] = Wk2[k*4096 + d*64 + f]
__global__ void permute_wk2(const float* __restrict__ Wk2) {
    int idx = blockIdx.x * blockDim.x + threadIdx.x;
    if (idx >= KWN * DIMV * DIMV) return;
    int k = idx >> 12;          // /4096
    int r = idx & 4095;
    int d = r >> 6;
    int f = r & 63;
    g_W2T[(size_t)d * (KWN * DIMV) + k * DIMV + f] = Wk2[idx];
}

// ---------------- generic tiled SGEMM (FFMA2 inner): C = act(A@B + bias) ----------------
template <bool RELU>
__global__ void __launch_bounds__(256, 2)
sgemm(const float* __restrict__ A, const float* __restrict__ B,
      const float* __restrict__ bias, float* __restrict__ C,
      int M, int N, int K) {
    __shared__ __align__(16) float As[16][132];   // transposed [k][m], padded
    __shared__ __align__(16) float Bs[16][128];
    int bm = blockIdx.y * 128, bn = blockIdx.x * 128;
    int tid = threadIdx.x;
    int tr = tid >> 4, tc = tid & 15;
    bool k4 = ((K & 3) == 0);

    u64t acc2[8][4];
#pragma unroll
    for (int i = 0; i < 8; i++)
#pragma unroll
        for (int j = 0; j < 4; j++) acc2[i][j] = 0ull;

    for (int kt = 0; kt < K; kt += 16) {
        // A tile 128x16 -> As[k][m]
#pragma unroll
        for (int l = 0; l < 2; l++) {
            int lin = tid + l * 256;
            int row = lin >> 2;
            int kq  = (lin & 3) * 4;
            float4 v = make_float4(0.f, 0.f, 0.f, 0.f);
            int gr = bm + row;
            if (gr < M) {
                int k0 = kt + kq;
                if (k4 && k0 + 3 < K) {
                    v = *(const float4*)&A[(size_t)gr * K + k0];
                } else {
                    float t0[4] = {0.f, 0.f, 0.f, 0.f};
#pragma unroll
                    for (int i = 0; i < 4; i++)
                        if (k0 + i < K) t0[i] = A[(size_t)gr * K + k0 + i];
                    v = make_float4(t0[0], t0[1], t0[2], t0[3]);
                }
            }
            As[kq + 0][row] = v.x; As[kq + 1][row] = v.y;
            As[kq + 2][row] = v.z; As[kq + 3][row] = v.w;
        }
        // B tile 16x128 (all B matrices have N % 4 == 0 -> rows 16B-aligned)
#pragma unroll
        for (int l = 0; l < 2; l++) {
            int lin = tid + l * 256;
            int kr = lin >> 5;
            int nq = (lin & 31) * 4;
            float4 v = make_float4(0.f, 0.f, 0.f, 0.f);
            int gk = kt + kr, gn = bn + nq;
            if (gk < K && gn + 3 < N)
                v = *(const float4*)&B[(size_t)gk * N + gn];
            *(float4*)&Bs[kr][nq] = v;
        }
        __syncthreads();
#pragma unroll
        for (int k = 0; k < 16; k++) {
            float a[8];
            *(float4*)&a[0] = *(const float4*)&As[k][tr * 8];
            *(float4*)&a[4] = *(const float4*)&As[k][tr * 8 + 4];
            u64t b2[4];
            const u64t* bp = (const u64t*)&Bs[k][tc * 8];
            b2[0] = bp[0]; b2[1] = bp[1]; b2[2] = bp[2]; b2[3] = bp[3];
#pragma unroll
            for (int i = 0; i < 8; i++) {
                u64t ad = pack_dup(a[i]);
#pragma unroll
                for (int j = 0; j < 4; j++) fma2(acc2[i][j], ad, b2[j]);
            }
        }
        __syncthreads();
    }
#pragma unroll
    for (int i = 0; i < 8; i++) {
        int gr = bm + tr * 8 + i;
        if (gr >= M) continue;
#pragma unroll
        for (int j = 0; j < 4; j++) {
            float2 p = *(float2*)&acc2[i][j];
            int gn0 = bn + tc * 8 + 2 * j;
#pragma unroll
            for (int s = 0; s < 2; s++) {
                int gn = gn0 + s;
                if (gn >= N) continue;
                float v = (s == 0) ? p.x : p.y;
                if (bias) v += bias[gn];
                if (RELU) v = fmaxf(v, 0.f);
                C[(size_t)gr * N + gn] = v;
            }
        }
    }
}

// ---------------- attention path ----------------
__global__ void score_kernel(const int* __restrict__ ei_mf, const float* __restrict__ ea_mf,
                             const float* __restrict__ We) {
    __shared__ float sWe[6 * 64];
    int tid = threadIdx.x;
    for (int i = tid; i < 6 * 64; i += blockDim.x) sWe[i] = We[i];
    __syncthreads();
    int e = blockIdx.x * 8 + (tid >> 5);
    if (e >= EMFN) return;
    int l = tid & 31;
    int src = ei_mf[e];
    int dst = ei_mf[EMFN + e];
    float ke0 = g_kk[src * 64 + l];
    float ke1 = g_kk[src * 64 + 32 + l];
#pragma unroll
    for (int j = 0; j < 6; j++) {
        float ea = ea_mf[e * 6 + j];
        ke0 = fmaf(ea, sWe[j * 64 + l], ke0);
        ke1 = fmaf(ea, sWe[j * 64 + 32 + l], ke1);
    }
    float s = g_q[dst * 64 + l] * ke0 + g_q[dst * 64 + 32 + l] * ke1;
#pragma unroll
    for (int off = 16; off; off >>= 1) s += __shfl_down_sync(0xffffffffu, s, off);
    if (l == 0) {
        s *= 0.125f;   // 1/sqrt(64)
        g_score[e] = s;
        atomicMax(&g_mkey[dst], kenc(s));
    }
}

__global__ void exp_kernel(const int* __restrict__ ei_mf) {
    int e = blockIdx.x * blockDim.x + threadIdx.x;
    if (e >= EMFN) return;
    int dst = ei_mf[EMFN + e];
    float a = expf(g_score[e] - kdec(g_mkey[dst]));
    g_av[e] = a;
    atomicAdd(&g_z[dst], a);
}

__global__ void xcacc_kernel(const int* __restrict__ ei_mf) {
    int e = blockIdx.x * 8 + (threadIdx.x >> 5);
    if (e >= EMFN) return;
    int l = threadIdx.x & 31;
    int src = ei_mf[e];
    int dst = ei_mf[EMFN + e];
    float alpha = g_av[e] / (g_z[dst] + 1e-9f);
    atomicAdd(&g_xc[dst * 64 + l],      alpha * g_v[src * 64 + l]);
    atomicAdd(&g_xc[dst * 64 + 32 + l], alpha * g_v[src * 64 + 32 + l]);
}

// base = x_flow@Wroot + broot + x_cross@Wo + bo
__global__ void dual64_kernel(const float* __restrict__ x, const float* __restrict__ Wroot,
                              const float* __restrict__ broot, const float* __restrict__ Wo,
                              const float* __restrict__ bo) {
    __shared__ float sWr[64 * 64], sWo[64 * 64], sx[4][64], sxc[4][64];
    int tid = threadIdx.x;
    for (int i = tid; i < 4096; i += 256) { sWr[i] = Wroot[i]; sWo[i] = Wo[i]; }
    int r0 = blockIdx.x * 4;
    {
        int rr = tid >> 6, cc = tid & 63;
        int gr = r0 + rr;
        sx[rr][cc]  = (gr < NF) ? x[gr * 64 + cc]    : 0.f;
        sxc[rr][cc] = (gr < NF) ? g_xc[gr * 64 + cc] : 0.f;
    }
    __syncthreads();
    int rr = tid >> 6, cc = tid & 63;
    int gr = r0 + rr;
    if (gr < NF) {
        float s = broot[cc] + bo[cc];
#pragma unroll 8
        for (int d = 0; d < 64; d++)
            s += sx[rr][d] * sWr[d * 64 + cc] + sxc[rr][d] * sWo[d * 64 + cc];
        g_base[gr * 64 + cc] = s;
    }
}

// ---------------- CSR by src over ff-edges ----------------
__global__ void cnt_kernel(const int* __restrict__ ei_ff) {
    int e = blockIdx.x * blockDim.x + threadIdx.x;
    if (e < EFFN) atomicAdd(&g_cnt[ei_ff[e]], 1);
}

__global__ void scan_kernel() {
    __shared__ int s[1024];
    __shared__ int carry;
    int tid = threadIdx.x;
    if (tid == 0) carry = 0;
    __syncthreads();
    for (int base = 0; base < NF; base += 1024) {
        int i = base + tid;
        int v = (i < NF) ? g_cnt[i] : 0;
        s[tid] = v;
        __syncthreads();
        for (int off = 1; off < 1024; off <<= 1) {
            int t = (tid >= off) ? s[tid - off] : 0;
            __syncthreads();
            s[tid] += t;
            __syncthreads();
        }
        if (i < NF) { int ex = carry + s[tid] - v; g_off[i] = ex; g_pos[i] = ex; }
        __syncthreads();
        if (tid == 0) carry += s[1023];
        __syncthreads();
    }
    if (tid == 0) g_off[NF] = carry;
}

__global__ void fill_kernel(const int* __restrict__ ei_ff) {
    int e = blockIdx.x * blockDim.x + threadIdx.x;
    if (e < EFFN) {
        int p = atomicAdd(&g_pos[ei_ff[e]], 1);
        g_perm[p] = e;
    }
}

// ---------------- phase B: per-node msg = h[e] @ M[node] -> atomic aggr[dst] ----------------
__global__ void __launch_bounds__(256)
msg_kernel(const int* __restrict__ ei_ff, int slab) {
    __shared__ __align__(16) float Ms[128][64];
    __shared__ __align__(16) float hs[8][128];
    __shared__ float red[8][4][64];
    int tid = threadIdx.x;
    int nl = blockIdx.x;                // node within slab
    int n  = slab * SLAB + nl;
    int begin = g_off[n], end = g_off[n + 1];
    if (begin == end) return;
    int f = tid & 63, slice = tid >> 6;
    const float* Mrow = g_M + (size_t)nl * (KWN * DIMV);
    float cbias = g_c[n * 64 + f];

    for (int e0 = begin; e0 < end; e0 += 8) {
        int ec = min(8, end - e0);
        u64t acc2[8];
#pragma unroll
        for (int j = 0; j < 8; j++) acc2[j] = 0ull;

        for (int kt = 0; kt < 4; kt++) {
#pragma unroll
            for (int l = 0; l < 8; l++) {
                int lin = tid + l * 256;
                int k = lin >> 4;
                int fq = (lin & 15) * 4;
                *(float4*)&Ms[k][fq] = *(const float4*)&Mrow[(kt * 128 + k) * 64 + fq];
            }
            {
                int j  = tid >> 5;
                int kq = (tid & 31) * 4;
                float4 v = make_float4(0.f, 0.f, 0.f, 0.f);
                if (j < ec) {
                    int e = g_perm[e0 + j];
                    v = *(const float4*)&g_h[(size_t)e * KWN + kt * 128 + kq];
                }
                *(float4*)&hs[j][kq] = v;
            }
            __syncthreads();
            // process 2 k per iter: f32x2 lanes hold k-even / k-odd partials
#pragma unroll
            for (int kk2 = 0; kk2 < 16; kk2++) {
                int k = slice * 32 + kk2 * 2;
                u64t m2 = pack2(Ms[k][f], Ms[k + 1][f]);
#pragma unroll
                for (int j = 0; j < 8; j++) {
                    u64t h2 = *(const u64t*)&hs[j][k];   // contiguous k,k+1
                    fma2(acc2[j], h2, m2);
                }
            }
            __syncthreads();
        }
        for (int j = 0; j < ec; j++) {
            float2 p = *(float2*)&acc2[j];
            red[j][slice][f] = p.x + p.y;
        }
        __syncthreads();
        for (int jb = 0; jb < ec; jb += 4) {
            int j = jb + (tid >> 6);
            if (j < ec) {
                float s = red[j][0][f] + red[j][1][f] + red[j][2][f] + red[j][3][f] + cbias;
                int e = g_perm[e0 + j];
                int dst = ei_ff[EFFN + e];
                atomicAdd(&g_aggr[dst * 64 + f], s);
            }
        }
        __syncthreads();
    }
}

// ---------------- FiLM epilogue ----------------
__global__ void ss_kernel(const float* __restrict__ tau, const float* __restrict__ Wt1,
                          const float* __restrict__ bt1, const float* __restrict__ Wt2,
                          const float* __restrict__ bt2) {
    __shared__ float temb[64];
    int tid = threadIdx.x;
    if (tid < 64) temb[tid] = silu(tau[0] * Wt1[tid] + bt1[tid]);
    __syncthreads();
    if (tid < 128) {
        float s = bt2[tid];
        for (int d = 0; d < 64; d++) s += temb[d] * Wt2[d * 128 + tid];
        g_ss[tid] = s;
    }
}

__global__ void final_kernel(float* __restrict__ out) {
    int idx = blockIdx.x * blockDim.x + threadIdx.x;
    if (idx >= NF * 64) return;
    int fcol = idx & 63;
    float g = g_base[idx] + g_aggr[idx];
    g = fmaxf(g, 0.f);
    float y = g * (1.f + g_ss[fcol]) + g_ss[64 + fcol];
    out[idx] = silu(y);
}

// ---------------- host ----------------
extern "C" void kernel_launch(void* const* d_in, const int* in_sizes, int n_in,
                              void* d_out, int out_size) {
    const float* x_flow = (const float*)d_in[0];
    const float* x_memb = (const float*)d_in[1];
    const int *ei_ff, *ei_mf;
    const float *ea_ff, *ea_mf, *tau;
    if (in_sizes[2] == 2 * EFFN) {         // reference-signature order
        ei_ff = (const int*)d_in[2];  ea_ff = (const float*)d_in[3];
        ei_mf = (const int*)d_in[4];  ea_mf = (const float*)d_in[5];
        tau   = (const float*)d_in[6];
    } else {                               // setup_inputs dict order
        ea_ff = (const float*)d_in[2]; ea_mf = (const float*)d_in[3];
        tau   = (const float*)d_in[4];
        ei_ff = (const int*)d_in[5];   ei_mf = (const int*)d_in[6];
    }
    const float* Wk0   = (const float*)d_in[7];
    const float* bk0   = (const float*)d_in[8];
    const float* Wk1   = (const float*)d_in[9];
    const float* bk1   = (const float*)d_in[10];
    const float* Wk2   = (const float*)d_in[11];
    const float* bk2   = (const float*)d_in[12];
    const float* Wroot = (const float*)d_in[13];
    const float* broot = (const float*)d_in[14];
    const float* Wq    = (const float*)d_in[15];
    const float* Wkk   = (const float*)d_in[16];
    const float* Wv    = (const float*)d_in[17];
    const float* We    = (const float*)d_in[18];
    const float* Wo    = (const float*)d_in[19];
    const float* bo    = (const float*)d_in[20];
    const float* Wt1   = (const float*)d_in[21];
    const float* bt1   = (const float*)d_in[22];
    const float* Wt2   = (const float*)d_in[23];
    const float* bt2   = (const float*)d_in[24];
    float* out = (float*)d_out;

    unsigned *p_mkey; float *p_z, *p_xc, *p_aggr; int* p_cnt;
    cudaGetSymbolAddress((void**)&p_mkey, g_mkey);
    cudaGetSymbolAddress((void**)&p_z,    g_z);
    cudaGetSymbolAddress((void**)&p_xc,   g_xc);
    cudaGetSymbolAddress((void**)&p_aggr, g_aggr);
    cudaGetSymbolAddress((void**)&p_cnt,  g_cnt);
    float *p_q, *p_kk, *p_v, *p_c, *p_h0, *p_h, *p_M, *p_W2T;
    cudaGetSymbolAddress((void**)&p_q,   g_q);
    cudaGetSymbolAddress((void**)&p_kk,  g_kk);
    cudaGetSymbolAddress((void**)&p_v,   g_v);
    cudaGetSymbolAddress((void**)&p_c,   g_c);
    cudaGetSymbolAddress((void**)&p_h0,  g_h0);
    cudaGetSymbolAddress((void**)&p_h,   g_h);
    cudaGetSymbolAddress((void**)&p_M,   g_M);
    cudaGetSymbolAddress((void**)&p_W2T, g_W2T);

    // init
    zero_u32<<<160, 256>>>(p_mkey, NF);
    zero_u32<<<160, 256>>>((unsigned*)p_z, NF);
    zero_u32<<<640, 256>>>((unsigned*)p_xc, NF * 64);
    zero_u32<<<640, 256>>>((unsigned*)p_aggr, NF * 64);
    zero_u32<<<160, 256>>>((unsigned*)p_cnt, NF);
    permute_wk2<<<(KWN * DIMV * DIMV + 255) / 256, 256>>>(Wk2);

    // small GEMMs: q, k, v, c
    {
        dim3 g1(1, (NF + 127) / 128);
        sgemm<false><<<g1, 256>>>(x_flow, Wq, nullptr, p_q, NF, 64, 64);
        dim3 g2(1, (NMB + 127) / 128);
        sgemm<false><<<g2, 256>>>(x_memb, Wkk, nullptr, p_kk, NMB, 64, 64);
        sgemm<false><<<g2, 256>>>(x_memb, Wv, nullptr, p_v, NMB, 64, 64);
        sgemm<false><<<g1, 256>>>(x_flow, bk2, nullptr, p_c, NF, 64, 64);
    }

    // attention path
    score_kernel<<<(EMFN + 7) / 8, 256>>>(ei_mf, ea_mf, We);
    exp_kernel<<<(EMFN + 255) / 256, 256>>>(ei_mf);
    xcacc_kernel<<<(EMFN + 7) / 8, 256>>>(ei_mf);
    dual64_kernel<<<(NF + 3) / 4, 256>>>(x_flow, Wroot, broot, Wo, bo);

    // edge MLP
    sgemm<true><<<dim3(4, (EFFN + 127) / 128), 256>>>(ea_ff, Wk0, bk0, p_h0, EFFN, KWN, 6);
    sgemm<true><<<dim3(4, (EFFN + 127) / 128), 256>>>(p_h0, Wk1, bk1, p_h, EFFN, KWN, KWN);

    // CSR by src
    cnt_kernel<<<(EFFN + 255) / 256, 256>>>(ei_ff);
    scan_kernel<<<1, 1024>>>();
    fill_kernel<<<(EFFN + 255) / 256, 256>>>(ei_ff);

    // slabbed phase A (M = x_slab @ W2T) + phase B (msg/aggr)
    for (int s = 0; s < NSLAB; s++) {
        sgemm<false><<<dim3(KWN * DIMV / 128, (SLAB + 127) / 128), 256>>>(
            x_flow + (size_t)s * SLAB * DIMV, p_W2T, nullptr, p_M,
            SLAB, KWN * DIMV, DIMV);
        msg_kernel<<<SLAB, 256>>>(ei_ff, s);
    }

    // FiLM epilogue
    ss_kernel<<<1, 128>>>(tau, Wt1, bt1, Wt2, bt2);
    final_kernel<<<(NF * 64 + 255) / 256, 256>>>(out);
}

// round 9
// speedup vs baseline: 2.2007x; 1.8237x over previous
#include <cuda_runtime.h>
#include <cuda_bf16.h>
#include <math.h>
#include <stdint.h>

#define NF    20000
#define NMB   5000
#define EFFN  100000
#define EMFN  80000
#define DIMV  64
#define KWN   512
#define SLAB  500
#define NSLAB 40
#define W2N   32768            // KWN * DIMV

#define A_LD  24               // 16 k + 8 pad (bf16)
#define B_LD  136              // 128 n + 8 pad (bf16)

typedef unsigned long long u64t;

// ---------------- device scratch (__device__ globals; no allocations) ----------------
__device__ float    g_h0[(size_t)EFFN * KWN];        // 204.8 MB
__device__ float    g_h [(size_t)EFFN * KWN];        // 204.8 MB
__device__ float    g_M [(size_t)SLAB * W2N];        // 65.5 MB per-slab M
__device__ unsigned short g_W2T_hi[(size_t)DIMV * W2N]; // 4 MB  [d][n=k*64+f]
__device__ unsigned short g_W2T_lo[(size_t)DIMV * W2N];
__device__ unsigned short g_Wk1_hi[KWN * KWN];       // 512 KB [k][n]
__device__ unsigned short g_Wk1_lo[KWN * KWN];
__device__ float    g_q [NF * DIMV];
__device__ float    g_kk[NMB * DIMV];
__device__ float    g_v [NMB * DIMV];
__device__ float    g_c [NF * DIMV];
__device__ float    g_score[EMFN];
__device__ float    g_av[EMFN];
__device__ unsigned g_mkey[NF];
__device__ float    g_z[NF];
__device__ float    g_xc[NF * DIMV];
__device__ float    g_base[NF * DIMV];
__device__ float    g_aggr[NF * DIMV];
__device__ int      g_cnt[NF];
__device__ int      g_off[NF + 1];
__device__ int      g_pos[NF];
__device__ int      g_perm[EFFN];
__device__ float    g_ss[2 * DIMV];

// ---------------- helpers ----------------
__device__ __forceinline__ unsigned kenc(float f) {
    unsigned b = __float_as_uint(f);
    return (b & 0x80000000u) ? ~b : (b | 0x80000000u);
}
__device__ __forceinline__ float kdec(unsigned u) {
    return (u & 0x80000000u) ? __uint_as_float(u ^ 0x80000000u) : __uint_as_float(~u);
}
__device__ __forceinline__ float silu(float y) { return y / (1.f + expf(-y)); }

__device__ __forceinline__ u64t pack_dup(float x) {
    u64t r; asm("mov.b64 %0, {%1, %1};" : "=l"(r) : "r"(__float_as_uint(x))); return r;
}
__device__ __forceinline__ u64t pack2(float lo, float hi) {
    u64t r; asm("mov.b64 %0, {%1, %2};" : "=l"(r) : "r"(__float_as_uint(lo)), "r"(__float_as_uint(hi))); return r;
}
__device__ __forceinline__ void fma2(u64t& d, u64t a, u64t b) {
    asm("fma.rn.f32x2 %0, %1, %2, %0;" : "+l"(d) : "l"(a), "l"(b));
}

__device__ __forceinline__ uint32_t smem_u32(const void* p) {
    uint32_t a;
    asm("{ .reg .u64 t; cvta.to.shared.u64 t, %1; cvt.u32.u64 %0, t; }" : "=r"(a) : "l"(p));
    return a;
}
__device__ __forceinline__ void ldsm4(uint32_t& r0, uint32_t& r1, uint32_t& r2, uint32_t& r3, uint32_t a) {
    asm volatile("ldmatrix.sync.aligned.m8n8.x4.shared.b16 {%0,%1,%2,%3}, [%4];"
        : "=r"(r0), "=r"(r1), "=r"(r2), "=r"(r3) : "r"(a));
}
__device__ __forceinline__ void ldsm4t(uint32_t& r0, uint32_t& r1, uint32_t& r2, uint32_t& r3, uint32_t a) {
    asm volatile("ldmatrix.sync.aligned.m8n8.x4.trans.shared.b16 {%0,%1,%2,%3}, [%4];"
        : "=r"(r0), "=r"(r1), "=r"(r2), "=r"(r3) : "r"(a));
}
__device__ __forceinline__ void mma_bf16(float* c, const uint32_t* a, uint32_t b0, uint32_t b1) {
    asm volatile(
        "mma.sync.aligned.m16n8k16.row.col.f32.bf16.bf16.f32 "
        "{%0,%1,%2,%3}, {%4,%5,%6,%7}, {%8,%9}, {%0,%1,%2,%3};"
        : "+f"(c[0]), "+f"(c[1]), "+f"(c[2]), "+f"(c[3])
        : "r"(a[0]), "r"(a[1]), "r"(a[2]), "r"(a[3]), "r"(b0), "r"(b1));
}

// hi/lo split of 8 consecutive floats -> two 16B packets
__device__ __forceinline__ void split8(const float* s, uint4& hi, uint4& lo) {
    unsigned short h[8], l[8];
#pragma unroll
    for (int i = 0; i < 8; i++) {
        float f = s[i];
        __nv_bfloat16 bh = __float2bfloat16_rn(f);
        __nv_bfloat16 bl = __float2bfloat16_rn(f - __bfloat162float(bh));
        h[i] = __bfloat16_as_ushort(bh);
        l[i] = __bfloat16_as_ushort(bl);
    }
    hi.x = h[0] | ((unsigned)h[1] << 16); hi.y = h[2] | ((unsigned)h[3] << 16);
    hi.z = h[4] | ((unsigned)h[5] << 16); hi.w = h[6] | ((unsigned)h[7] << 16);
    lo.x = l[0] | ((unsigned)l[1] << 16); lo.y = l[2] | ((unsigned)l[3] << 16);
    lo.z = l[4] | ((unsigned)l[5] << 16); lo.w = l[6] | ((unsigned)l[7] << 16);
}

// warp-tile kstep: c[2][8][4] += bf16x3( A[32x16] , B[16x64] )
__device__ __forceinline__ void warp_kstep(float c[2][8][4],
        const unsigned short* Ahi, const unsigned short* Alo,
        const unsigned short* Bhi, const unsigned short* Blo,
        int warp_m, int warp_n, int lane) {
    int arow = lane & 15;
    int acol = (lane >> 4) << 3;
    uint32_t ahi[2][4], alo[2][4];
#pragma unroll
    for (int mi = 0; mi < 2; mi++) {
        int r = warp_m * 32 + mi * 16 + arow;
        ldsm4(ahi[mi][0], ahi[mi][1], ahi[mi][2], ahi[mi][3], smem_u32(Ahi + r * A_LD + acol));
        ldsm4(alo[mi][0], alo[mi][1], alo[mi][2], alo[mi][3], smem_u32(Alo + r * A_LD + acol));
    }
#pragma unroll
    for (int nh = 0; nh < 2; nh++) {
        uint32_t bhi[2][4], blo[2][4];
#pragma unroll
        for (int ni = 0; ni < 2; ni++) {
            int ncol = warp_n * 64 + nh * 32 + ni * 16 + acol;
            ldsm4t(bhi[ni][0], bhi[ni][1], bhi[ni][2], bhi[ni][3], smem_u32(Bhi + arow * B_LD + ncol));
            ldsm4t(blo[ni][0], blo[ni][1], blo[ni][2], blo[ni][3], smem_u32(Blo + arow * B_LD + ncol));
        }
#pragma unroll
        for (int mi = 0; mi < 2; mi++)
#pragma unroll
            for (int ni = 0; ni < 2; ni++) {
                int n8 = nh * 4 + ni * 2;
                mma_bf16(c[mi][n8],     ahi[mi], bhi[ni][0], bhi[ni][1]);
                mma_bf16(c[mi][n8 + 1], ahi[mi], bhi[ni][2], bhi[ni][3]);
                mma_bf16(c[mi][n8],     ahi[mi], blo[ni][0], blo[ni][1]);
                mma_bf16(c[mi][n8 + 1], ahi[mi], blo[ni][2], blo[ni][3]);
                mma_bf16(c[mi][n8],     alo[mi], bhi[ni][0], bhi[ni][1]);
                mma_bf16(c[mi][n8 + 1], alo[mi], bhi[ni][2], bhi[ni][3]);
            }
    }
}

// ---------------- tiny utility kernels ----------------
__global__ void zero_u32(unsigned* p, int n) {
    for (int i = blockIdx.x * blockDim.x + threadIdx.x; i < n; i += gridDim.x * blockDim.x)
        p[i] = 0u;
}

// Wk1 [k][n] -> hi/lo
__global__ void conv_wk1(const float* __restrict__ Wk1) {
    int idx = blockIdx.x * blockDim.x + threadIdx.x;
    if (idx >= KWN * KWN) return;
    float v = Wk1[idx];
    __nv_bfloat16 bh = __float2bfloat16_rn(v);
    __nv_bfloat16 bl = __float2bfloat16_rn(v - __bfloat162float(bh));
    g_Wk1_hi[idx] = __bfloat16_as_ushort(bh);
    g_Wk1_lo[idx] = __bfloat16_as_ushort(bl);
}

// W2T[d][n=k*64+f] = Wk2[k*4096 + d*64 + f] -> hi/lo
__global__ void conv_w2t(const float* __restrict__ Wk2) {
    int idx = blockIdx.x * blockDim.x + threadIdx.x;
    if (idx >= DIMV * W2N) return;
    int d = idx >> 15;
    int r = idx & 32767;
    int k = r >> 6;
    int f = r & 63;
    float v = Wk2[k * 4096 + d * 64 + f];
    __nv_bfloat16 bh = __float2bfloat16_rn(v);
    __nv_bfloat16 bl = __float2bfloat16_rn(v - __bfloat162float(bh));
    g_W2T_hi[idx] = __bfloat16_as_ushort(bh);
    g_W2T_lo[idx] = __bfloat16_as_ushort(bl);
}

// ---------------- HMMA GEMM 1: h = relu(h0 @ Wk1 + bk1) ----------------
__global__ void __launch_bounds__(256)
gemm_h_mma(const float* __restrict__ bk1) {
    __shared__ __align__(16) unsigned short Ahi[128 * A_LD], Alo[128 * A_LD];
    __shared__ __align__(16) unsigned short Bhi[16 * B_LD],  Blo[16 * B_LD];
    int tid = threadIdx.x, wid = tid >> 5, lane = tid & 31;
    int warp_m = wid & 3, warp_n = wid >> 2;
    int tm = blockIdx.y, tn = blockIdx.x;

    float c[2][8][4];
#pragma unroll
    for (int i = 0; i < 2; i++)
#pragma unroll
        for (int j = 0; j < 8; j++)
#pragma unroll
            for (int q = 0; q < 4; q++) c[i][j][q] = 0.f;

    for (int kc = 0; kc < KWN / 16; kc++) {
        // stage A: 128x16 fp32 -> hi/lo bf16
        {
            int r = tid >> 1, kq = (tid & 1) * 8;
            int grow = tm * 128 + r;
            uint4 hi, lo;
            if (grow < EFFN) {
                float buf[8];
                const float* src = g_h0 + (size_t)grow * KWN + kc * 16 + kq;
                *(float4*)&buf[0] = *(const float4*)src;
                *(float4*)&buf[4] = *(const float4*)(src + 4);
                split8(buf, hi, lo);
            } else { hi = make_uint4(0, 0, 0, 0); lo = hi; }
            *(uint4*)&Ahi[r * A_LD + kq] = hi;
            *(uint4*)&Alo[r * A_LD + kq] = lo;
        }
        // stage B: 16x128 from preconverted Wk1 (coalesced)
        {
            int k = tid >> 4, nq = (tid & 15) * 8;
            size_t src = (size_t)(kc * 16 + k) * KWN + tn * 128 + nq;
            *(uint4*)&Bhi[k * B_LD + nq] = *(const uint4*)&g_Wk1_hi[src];
            *(uint4*)&Blo[k * B_LD + nq] = *(const uint4*)&g_Wk1_lo[src];
        }
        __syncthreads();
        warp_kstep(c, Ahi, Alo, Bhi, Blo, warp_m, warp_n, lane);
        __syncthreads();
    }

    // epilogue: bias + relu, direct float2 stores
    int rbase = tm * 128 + warp_m * 32 + (lane >> 2);
    int cbase = tn * 128 + warp_n * 64 + (lane & 3) * 2;
#pragma unroll
    for (int mi = 0; mi < 2; mi++) {
#pragma unroll
        for (int n8 = 0; n8 < 8; n8++) {
            int col = cbase + n8 * 8;
            float b0 = bk1[col], b1 = bk1[col + 1];
            int r0 = rbase + mi * 16;
            if (r0 < EFFN) {
                float2 v = make_float2(fmaxf(c[mi][n8][0] + b0, 0.f), fmaxf(c[mi][n8][1] + b1, 0.f));
                *(float2*)&g_h[(size_t)r0 * KWN + col] = v;
            }
            int r1 = r0 + 8;
            if (r1 < EFFN) {
                float2 v = make_float2(fmaxf(c[mi][n8][2] + b0, 0.f), fmaxf(c[mi][n8][3] + b1, 0.f));
                *(float2*)&g_h[(size_t)r1 * KWN + col] = v;
            }
        }
    }
}

// ---------------- HMMA GEMM 2: M_slab = x_slab @ W2T  [512 x 32768], K=64 ----------------
__global__ void __launch_bounds__(256)
gemm_m_mma(const float* __restrict__ x_flow, int slab) {
    __shared__ __align__(16) unsigned short Ahi[128 * A_LD], Alo[128 * A_LD];
    __shared__ __align__(16) unsigned short Bhi[16 * B_LD],  Blo[16 * B_LD];
    int tid = threadIdx.x, wid = tid >> 5, lane = tid & 31;
    int warp_m = wid & 3, warp_n = wid >> 2;
    int tm = blockIdx.y, tn = blockIdx.x;

    float c[2][8][4];
#pragma unroll
    for (int i = 0; i < 2; i++)
#pragma unroll
        for (int j = 0; j < 8; j++)
#pragma unroll
            for (int q = 0; q < 4; q++) c[i][j][q] = 0.f;

    for (int kc = 0; kc < DIMV / 16; kc++) {
        {
            int r = tid >> 1, kq = (tid & 1) * 8;
            int rl = tm * 128 + r;
            uint4 hi, lo;
            if (rl < SLAB) {
                float buf[8];
                const float* src = x_flow + ((size_t)slab * SLAB + rl) * DIMV + kc * 16 + kq;
                *(float4*)&buf[0] = *(const float4*)src;
                *(float4*)&buf[4] = *(const float4*)(src + 4);
                split8(buf, hi, lo);
            } else { hi = make_uint4(0, 0, 0, 0); lo = hi; }
            *(uint4*)&Ahi[r * A_LD + kq] = hi;
            *(uint4*)&Alo[r * A_LD + kq] = lo;
        }
        {
            int k = tid >> 4, nq = (tid & 15) * 8;
            size_t src = (size_t)(kc * 16 + k) * W2N + tn * 128 + nq;
            *(uint4*)&Bhi[k * B_LD + nq] = *(const uint4*)&g_W2T_hi[src];
            *(uint4*)&Blo[k * B_LD + nq] = *(const uint4*)&g_W2T_lo[src];
        }
        __syncthreads();
        warp_kstep(c, Ahi, Alo, Bhi, Blo, warp_m, warp_n, lane);
        __syncthreads();
    }

    int rbase = tm * 128 + warp_m * 32 + (lane >> 2);
    int cbase = tn * 128 + warp_n * 64 + (lane & 3) * 2;
#pragma unroll
    for (int mi = 0; mi < 2; mi++) {
#pragma unroll
        for (int n8 = 0; n8 < 8; n8++) {
            int col = cbase + n8 * 8;
            int r0 = rbase + mi * 16;
            if (r0 < SLAB)
                *(float2*)&g_M[(size_t)r0 * W2N + col] = make_float2(c[mi][n8][0], c[mi][n8][1]);
            int r1 = r0 + 8;
            if (r1 < SLAB)
                *(float2*)&g_M[(size_t)r1 * W2N + col] = make_float2(c[mi][n8][2], c[mi][n8][3]);
        }
    }
}

// ---------------- generic tiled SGEMM (FFMA2): small GEMMs + h0 ----------------
template <bool RELU>
__global__ void __launch_bounds__(256, 2)
sgemm(const float* __restrict__ A, const float* __restrict__ B,
      const float* __restrict__ bias, float* __restrict__ C,
      int M, int N, int K) {
    __shared__ __align__(16) float As[16][132];
    __shared__ __align__(16) float Bs[16][128];
    int bm = blockIdx.y * 128, bn = blockIdx.x * 128;
    int tid = threadIdx.x;
    int tr = tid >> 4, tc = tid & 15;
    bool k4 = ((K & 3) == 0);

    u64t acc2[8][4];
#pragma unroll
    for (int i = 0; i < 8; i++)
#pragma unroll
        for (int j = 0; j < 4; j++) acc2[i][j] = 0ull;

    for (int kt = 0; kt < K; kt += 16) {
#pragma unroll
        for (int l = 0; l < 2; l++) {
            int lin = tid + l * 256;
            int row = lin >> 2;
            int kq  = (lin & 3) * 4;
            float4 v = make_float4(0.f, 0.f, 0.f, 0.f);
            int gr = bm + row;
            if (gr < M) {
                int k0 = kt + kq;
                if (k4 && k0 + 3 < K) {
                    v = *(const float4*)&A[(size_t)gr * K + k0];
                } else {
                    float t0[4] = {0.f, 0.f, 0.f, 0.f};
#pragma unroll
                    for (int i = 0; i < 4; i++)
                        if (k0 + i < K) t0[i] = A[(size_t)gr * K + k0 + i];
                    v = make_float4(t0[0], t0[1], t0[2], t0[3]);
                }
            }
            As[kq + 0][row] = v.x; As[kq + 1][row] = v.y;
            As[kq + 2][row] = v.z; As[kq + 3][row] = v.w;
        }
#pragma unroll
        for (int l = 0; l < 2; l++) {
            int lin = tid + l * 256;
            int kr = lin >> 5;
            int nq = (lin & 31) * 4;
            float4 v = make_float4(0.f, 0.f, 0.f, 0.f);
            int gk = kt + kr, gn = bn + nq;
            if (gk < K && gn + 3 < N)
                v = *(const float4*)&B[(size_t)gk * N + gn];
            *(float4*)&Bs[kr][nq] = v;
        }
        __syncthreads();
#pragma unroll
        for (int k = 0; k < 16; k++) {
            float a[8];
            *(float4*)&a[0] = *(const float4*)&As[k][tr * 8];
            *(float4*)&a[4] = *(const float4*)&As[k][tr * 8 + 4];
            u64t b2[4];
            const u64t* bp = (const u64t*)&Bs[k][tc * 8];
            b2[0] = bp[0]; b2[1] = bp[1]; b2[2] = bp[2]; b2[3] = bp[3];
#pragma unroll
            for (int i = 0; i < 8; i++) {
                u64t ad = pack_dup(a[i]);
#pragma unroll
                for (int j = 0; j < 4; j++) fma2(acc2[i][j], ad, b2[j]);
            }
        }
        __syncthreads();
    }
#pragma unroll
    for (int i = 0; i < 8; i++) {
        int gr = bm + tr * 8 + i;
        if (gr >= M) continue;
#pragma unroll
        for (int j = 0; j < 4; j++) {
            float2 p = *(float2*)&acc2[i][j];
            int gn0 = bn + tc * 8 + 2 * j;
#pragma unroll
            for (int s = 0; s < 2; s++) {
                int gn = gn0 + s;
                if (gn >= N) continue;
                float v = (s == 0) ? p.x : p.y;
                if (bias) v += bias[gn];
                if (RELU) v = fmaxf(v, 0.f);
                C[(size_t)gr * N + gn] = v;
            }
        }
    }
}

// ---------------- attention path ----------------
__global__ void score_kernel(const int* __restrict__ ei_mf, const float* __restrict__ ea_mf,
                             const float* __restrict__ We) {
    __shared__ float sWe[6 * 64];
    int tid = threadIdx.x;
    for (int i = tid; i < 6 * 64; i += blockDim.x) sWe[i] = We[i];
    __syncthreads();
    int e = blockIdx.x * 8 + (tid >> 5);
    if (e >= EMFN) return;
    int l = tid & 31;
    int src = ei_mf[e];
    int dst = ei_mf[EMFN + e];
    float ke0 = g_kk[src * 64 + l];
    float ke1 = g_kk[src * 64 + 32 + l];
#pragma unroll
    for (int j = 0; j < 6; j++) {
        float ea = ea_mf[e * 6 + j];
        ke0 = fmaf(ea, sWe[j * 64 + l], ke0);
        ke1 = fmaf(ea, sWe[j * 64 + 32 + l], ke1);
    }
    float s = g_q[dst * 64 + l] * ke0 + g_q[dst * 64 + 32 + l] * ke1;
#pragma unroll
    for (int off = 16; off; off >>= 1) s += __shfl_down_sync(0xffffffffu, s, off);
    if (l == 0) {
        s *= 0.125f;
        g_score[e] = s;
        atomicMax(&g_mkey[dst], kenc(s));
    }
}

__global__ void exp_kernel(const int* __restrict__ ei_mf) {
    int e = blockIdx.x * blockDim.x + threadIdx.x;
    if (e >= EMFN) return;
    int dst = ei_mf[EMFN + e];
    float a = expf(g_score[e] - kdec(g_mkey[dst]));
    g_av[e] = a;
    atomicAdd(&g_z[dst], a);
}

__global__ void xcacc_kernel(const int* __restrict__ ei_mf) {
    int e = blockIdx.x * 8 + (threadIdx.x >> 5);
    if (e >= EMFN) return;
    int l = threadIdx.x & 31;
    int src = ei_mf[e];
    int dst = ei_mf[EMFN + e];
    float alpha = g_av[e] / (g_z[dst] + 1e-9f);
    atomicAdd(&g_xc[dst * 64 + l],      alpha * g_v[src * 64 + l]);
    atomicAdd(&g_xc[dst * 64 + 32 + l], alpha * g_v[src * 64 + 32 + l]);
}

__global__ void dual64_kernel(const float* __restrict__ x, const float* __restrict__ Wroot,
                              const float* __restrict__ broot, const float* __restrict__ Wo,
                              const float* __restrict__ bo) {
    __shared__ float sWr[64 * 64], sWo[64 * 64], sx[4][64], sxc[4][64];
    int tid = threadIdx.x;
    for (int i = tid; i < 4096; i += 256) { sWr[i] = Wroot[i]; sWo[i] = Wo[i]; }
    int r0 = blockIdx.x * 4;
    {
        int rr = tid >> 6, cc = tid & 63;
        int gr = r0 + rr;
        sx[rr][cc]  = (gr < NF) ? x[gr * 64 + cc]    : 0.f;
        sxc[rr][cc] = (gr < NF) ? g_xc[gr * 64 + cc] : 0.f;
    }
    __syncthreads();
    int rr = tid >> 6, cc = tid & 63;
    int gr = r0 + rr;
    if (gr < NF) {
        float s = broot[cc] + bo[cc];
#pragma unroll 8
        for (int d = 0; d < 64; d++)
            s += sx[rr][d] * sWr[d * 64 + cc] + sxc[rr][d] * sWo[d * 64 + cc];
        g_base[gr * 64 + cc] = s;
    }
}

// ---------------- CSR by src over ff-edges ----------------
__global__ void cnt_kernel(const int* __restrict__ ei_ff) {
    int e = blockIdx.x * blockDim.x + threadIdx.x;
    if (e < EFFN) atomicAdd(&g_cnt[ei_ff[e]], 1);
}

__global__ void scan_kernel() {
    __shared__ int s[1024];
    __shared__ int carry;
    int tid = threadIdx.x;
    if (tid == 0) carry = 0;
    __syncthreads();
    for (int base = 0; base < NF; base += 1024) {
        int i = base + tid;
        int v = (i < NF) ? g_cnt[i] : 0;
        s[tid] = v;
        __syncthreads();
        for (int off = 1; off < 1024; off <<= 1) {
            int t = (tid >= off) ? s[tid - off] : 0;
            __syncthreads();
            s[tid] += t;
            __syncthreads();
        }
        if (i < NF) { int ex = carry + s[tid] - v; g_off[i] = ex; g_pos[i] = ex; }
        __syncthreads();
        if (tid == 0) carry += s[1023];
        __syncthreads();
    }
    if (tid == 0) g_off[NF] = carry;
}

__global__ void fill_kernel(const int* __restrict__ ei_ff) {
    int e = blockIdx.x * blockDim.x + threadIdx.x;
    if (e < EFFN) {
        int p = atomicAdd(&g_pos[ei_ff[e]], 1);
        g_perm[p] = e;
    }
}

// ---------------- phase B: per-node msg = h[e] @ M[node] -> atomic aggr[dst] ----------------
__global__ void __launch_bounds__(256)
msg_kernel(const int* __restrict__ ei_ff, int slab) {
    __shared__ __align__(16) float Ms[128][64];
    __shared__ __align__(16) float hs[8][128];
    __shared__ float red[8][4][64];
    int tid = threadIdx.x;
    int nl = blockIdx.x;
    int n  = slab * SLAB + nl;
    int begin = g_off[n], end = g_off[n + 1];
    if (begin == end) return;
    int f = tid & 63, slice = tid >> 6;
    const float* Mrow = g_M + (size_t)nl * W2N;
    float cbias = g_c[n * 64 + f];

    for (int e0 = begin; e0 < end; e0 += 8) {
        int ec = min(8, end - e0);
        u64t acc2[8];
#pragma unroll
        for (int j = 0; j < 8; j++) acc2[j] = 0ull;

        for (int kt = 0; kt < 4; kt++) {
#pragma unroll
            for (int l = 0; l < 8; l++) {
                int lin = tid + l * 256;
                int k = lin >> 4;
                int fq = (lin & 15) * 4;
                *(float4*)&Ms[k][fq] = *(const float4*)&Mrow[(kt * 128 + k) * 64 + fq];
            }
            {
                int j  = tid >> 5;
                int kq = (tid & 31) * 4;
                float4 v = make_float4(0.f, 0.f, 0.f, 0.f);
                if (j < ec) {
                    int e = g_perm[e0 + j];
                    v = *(const float4*)&g_h[(size_t)e * KWN + kt * 128 + kq];
                }
                *(float4*)&hs[j][kq] = v;
            }
            __syncthreads();
#pragma unroll
            for (int kk2 = 0; kk2 < 16; kk2++) {
                int k = slice * 32 + kk2 * 2;
                u64t m2 = pack2(Ms[k][f], Ms[k + 1][f]);
#pragma unroll
                for (int j = 0; j < 8; j++) {
                    u64t h2 = *(const u64t*)&hs[j][k];
                    fma2(acc2[j], h2, m2);
                }
            }
            __syncthreads();
        }
        for (int j = 0; j < ec; j++) {
            float2 p = *(float2*)&acc2[j];
            red[j][slice][f] = p.x + p.y;
        }
        __syncthreads();
        for (int jb = 0; jb < ec; jb += 4) {
            int j = jb + (tid >> 6);
            if (j < ec) {
                float s = red[j][0][f] + red[j][1][f] + red[j][2][f] + red[j][3][f] + cbias;
                int e = g_perm[e0 + j];
                int dst = ei_ff[EFFN + e];
                atomicAdd(&g_aggr[dst * 64 + f], s);
            }
        }
        __syncthreads();
    }
}

// ---------------- FiLM epilogue ----------------
__global__ void ss_kernel(const float* __restrict__ tau, const float* __restrict__ Wt1,
                          const float* __restrict__ bt1, const float* __restrict__ Wt2,
                          const float* __restrict__ bt2) {
    __shared__ float temb[64];
    int tid = threadIdx.x;
    if (tid < 64) temb[tid] = silu(tau[0] * Wt1[tid] + bt1[tid]);
    __syncthreads();
    if (tid < 128) {
        float s = bt2[tid];
        for (int d = 0; d < 64; d++) s += temb[d] * Wt2[d * 128 + tid];
        g_ss[tid] = s;
    }
}

__global__ void final_kernel(float* __restrict__ out) {
    int idx = blockIdx.x * blockDim.x + threadIdx.x;
    if (idx >= NF * 64) return;
    int fcol = idx & 63;
    float g = g_base[idx] + g_aggr[idx];
    g = fmaxf(g, 0.f);
    float y = g * (1.f + g_ss[fcol]) + g_ss[64 + fcol];
    out[idx] = silu(y);
}

// ---------------- host ----------------
extern "C" void kernel_launch(void* const* d_in, const int* in_sizes, int n_in,
                              void* d_out, int out_size) {
    const float* x_flow = (const float*)d_in[0];
    const float* x_memb = (const float*)d_in[1];
    const int *ei_ff, *ei_mf;
    const float *ea_ff, *ea_mf, *tau;
    if (in_sizes[2] == 2 * EFFN) {
        ei_ff = (const int*)d_in[2];  ea_ff = (const float*)d_in[3];
        ei_mf = (const int*)d_in[4];  ea_mf = (const float*)d_in[5];
        tau   = (const float*)d_in[6];
    } else {
        ea_ff = (const float*)d_in[2]; ea_mf = (const float*)d_in[3];
        tau   = (const float*)d_in[4];
        ei_ff = (const int*)d_in[5];   ei_mf = (const int*)d_in[6];
    }
    const float* Wk0   = (const float*)d_in[7];
    const float* bk0   = (const float*)d_in[8];
    const float* Wk1   = (const float*)d_in[9];
    const float* bk1   = (const float*)d_in[10];
    const float* Wk2   = (const float*)d_in[11];
    const float* bk2   = (const float*)d_in[12];
    const float* Wroot = (const float*)d_in[13];
    const float* broot = (const float*)d_in[14];
    const float* Wq    = (const float*)d_in[15];
    const float* Wkk   = (const float*)d_in[16];
    const float* Wv    = (const float*)d_in[17];
    const float* We    = (const float*)d_in[18];
    const float* Wo    = (const float*)d_in[19];
    const float* bo    = (const float*)d_in[20];
    const float* Wt1   = (const float*)d_in[21];
    const float* bt1   = (const float*)d_in[22];
    const float* Wt2   = (const float*)d_in[23];
    const float* bt2   = (const float*)d_in[24];
    float* out = (float*)d_out;

    unsigned *p_mkey; float *p_z, *p_xc, *p_aggr; int* p_cnt;
    cudaGetSymbolAddress((void**)&p_mkey, g_mkey);
    cudaGetSymbolAddress((void**)&p_z,    g_z);
    cudaGetSymbolAddress((void**)&p_xc,   g_xc);
    cudaGetSymbolAddress((void**)&p_aggr, g_aggr);
    cudaGetSymbolAddress((void**)&p_cnt,  g_cnt);
    float *p_q, *p_kk, *p_v, *p_c, *p_h0;
    cudaGetSymbolAddress((void**)&p_q,   g_q);
    cudaGetSymbolAddress((void**)&p_kk,  g_kk);
    cudaGetSymbolAddress((void**)&p_v,   g_v);
    cudaGetSymbolAddress((void**)&p_c,   g_c);
    cudaGetSymbolAddress((void**)&p_h0,  g_h0);

    // init + weight conversion
    zero_u32<<<160, 256>>>(p_mkey, NF);
    zero_u32<<<160, 256>>>((unsigned*)p_z, NF);
    zero_u32<<<640, 256>>>((unsigned*)p_xc, NF * 64);
    zero_u32<<<640, 256>>>((unsigned*)p_aggr, NF * 64);
    zero_u32<<<160, 256>>>((unsigned*)p_cnt, NF);
    conv_wk1<<<(KWN * KWN + 255) / 256, 256>>>(Wk1);
    conv_w2t<<<(DIMV * W2N + 255) / 256, 256>>>(Wk2);

    // small GEMMs: q, k, v, c
    {
        dim3 g1(1, (NF + 127) / 128);
        sgemm<false><<<g1, 256>>>(x_flow, Wq, nullptr, p_q, NF, 64, 64);
        dim3 g2(1, (NMB + 127) / 128);
        sgemm<false><<<g2, 256>>>(x_memb, Wkk, nullptr, p_kk, NMB, 64, 64);
        sgemm<false><<<g2, 256>>>(x_memb, Wv, nullptr, p_v, NMB, 64, 64);
        sgemm<false><<<g1, 256>>>(x_flow, bk2, nullptr, p_c, NF, 64, 64);
    }

    // attention path
    score_kernel<<<(EMFN + 7) / 8, 256>>>(ei_mf, ea_mf, We);
    exp_kernel<<<(EMFN + 255) / 256, 256>>>(ei_mf);
    xcacc_kernel<<<(EMFN + 7) / 8, 256>>>(ei_mf);
    dual64_kernel<<<(NF + 3) / 4, 256>>>(x_flow, Wroot, broot, Wo, bo);

    // edge MLP: h0 (FFMA2, K=6), then h via HMMA bf16x3
    sgemm<true><<<dim3(4, (EFFN + 127) / 128), 256>>>(ea_ff, Wk0, bk0, p_h0, EFFN, KWN, 6);
    gemm_h_mma<<<dim3(4, (EFFN + 127) / 128), 256>>>(bk1);

    // CSR by src
    cnt_kernel<<<(EFFN + 255) / 256, 256>>>(ei_ff);
    scan_kernel<<<1, 1024>>>();
    fill_kernel<<<(EFFN + 255) / 256, 256>>>(ei_ff);

    // slabbed phase A (HMMA) + phase B
    for (int s = 0; s < NSLAB; s++) {
        gemm_m_mma<<<dim3(W2N / 128, 4), 256>>>(x_flow, s);
        msg_kernel<<<SLAB, 256>>>(ei_ff, s);
    }

    // FiLM epilogue
    ss_kernel<<<1, 128>>>(tau, Wt1, bt1, Wt2, bt2);
    final_kernel<<<(NF * 64 + 255) / 256, 256>>>(out);
}